// round 2
// baseline (speedup 1.0000x reference)
#include <cuda_runtime.h>
#include <cstdint>

#define NDOM 4
#define NB   8192
#define NF   128
#define BM   128
#define BN   128
#define NTHREADS 256
#define SMEM_BYTES ((2 * BM * NF) * 4 + BN * 4)

// Scratch for normalized int32 labels (no cudaMalloc allowed).
__device__ int g_labels[NDOM * NB];

// Labels may arrive as int64 or int32 (JAX x64 flag dependent). Values are in
// [0, 64). If int64 (little-endian, non-negative), every odd 32-bit word is 0.
// For random int32 labels the odd words are random -> detection is unambiguous.
__global__ void convert_labels_kernel(const unsigned int* __restrict__ w, int n) {
    __shared__ int s_any;
    if (threadIdx.x == 0) s_any = 0;
    __syncthreads();
    int any = 0;
    for (int i = threadIdx.x; i < n / 2; i += blockDim.x)
        any |= (w[2 * i + 1] != 0u);  // stays within n words even if int32
    if (any) atomicOr(&s_any, 1);
    __syncthreads();
    const bool is64 = (s_any == 0);
    for (int i = threadIdx.x; i < n; i += blockDim.x)
        g_labels[i] = is64 ? (int)w[2 * i] : (int)w[i];
}

// Cooperative tile loader: gmem [128 rows x 128 floats] row-major ->
// smem k-major [k][x] with XOR swizzle x' = x ^ (4*((k>>2)&7)).
// Per warp-step: 4 rows x 32 floats (coalesced 4x128B reads, conflict-free STS).
__device__ __forceinline__ void load_tile(float* __restrict__ dst,
                                          const float* __restrict__ src,
                                          int tid) {
    const int lane = tid & 31, warp = tid >> 5;
    const int jo = lane & 3;        // row offset 0..3
    const int ko = lane >> 2;       // chunk 0..7
#pragma unroll
    for (int it = 0; it < 16; ++it) {
        const int seg = it * 8 + warp;       // 0..127
        const int rb  = (seg >> 2) << 2;     // row base (mult of 4)
        const int q   = seg & 3;             // quarter of the row
        const int row = rb + jo;
        const int k0  = q * 32 + ko * 4;
        float4 v = *reinterpret_cast<const float4*>(src + (size_t)row * NF + k0);
        const int xj = row ^ (ko << 2);      // (k0>>2)&7 == ko
        dst[(k0 + 0) * BM + xj] = v.x;
        dst[(k0 + 1) * BM + xj] = v.y;
        dst[(k0 + 2) * BM + xj] = v.z;
        dst[(k0 + 3) * BM + xj] = v.w;
    }
}

__global__ __launch_bounds__(NTHREADS, 1)
void mine_kernel(const float* __restrict__ emb,
                 float* __restrict__ pos_dist, float* __restrict__ neg_dist,
                 float* __restrict__ pos_embed, float* __restrict__ neg_embed) {
    extern __shared__ float smem[];
    float* sA = smem;                  // 128x128 swizzled
    float* sB = smem + BM * NF;        // 128x128 swizzled
    int*   sLab = (int*)(smem + 2 * BM * NF);  // 128 labels of current j-tile

    const int tid = threadIdx.x;
    const int tx = tid & 15;           // col thread  (0..15)
    const int ty = tid >> 4;           // row thread  (0..15)
    const int d  = blockIdx.y;
    const int tb = blockIdx.x * BM;    // row-tile base within domain

    const float* __restrict__ embd = emb + (size_t)d * NB * NF;
    const int*   __restrict__ labd = g_labels + d * NB;

    // A tile (rows tb..tb+127), resident for whole kernel.
    load_tile(sA, embd + (size_t)tb * NF, tid);

    // Row labels for this thread's 8 rows: {p*64 + ty*4 + r}.
    int li[2][4];
#pragma unroll
    for (int p = 0; p < 2; ++p)
#pragma unroll
        for (int r = 0; r < 4; ++r)
            li[p][r] = labd[tb + p * 64 + ty * 4 + r];

    const float INF = __int_as_float(0x7f800000);
    float minp[2][4], maxn[2][4];
    int   pidx[2][4], nidx[2][4];
#pragma unroll
    for (int p = 0; p < 2; ++p)
#pragma unroll
        for (int r = 0; r < 4; ++r) {
            minp[p][r] = INF;  pidx[p][r] = 0;
            maxn[p][r] = -INF; nidx[p][r] = 0;
        }

    const float4* As4 = reinterpret_cast<const float4*>(sA);
    const float4* Bs4 = reinterpret_cast<const float4*>(sB);

    for (int jt = 0; jt < NB / BN; ++jt) {
        __syncthreads();  // protect sB / sLab reuse
        const int jbase = jt * BN;
        load_tile(sB, embd + (size_t)jbase * NF, tid);
        if (tid < BN) sLab[tid] = labd[jbase + tid];
        __syncthreads();

        float c[2][2][4][4];
#pragma unroll
        for (int p = 0; p < 2; ++p)
#pragma unroll
            for (int q = 0; q < 2; ++q)
#pragma unroll
                for (int r = 0; r < 4; ++r)
#pragma unroll
                    for (int s = 0; s < 4; ++s)
                        c[p][q][r][s] = 0.0f;

#pragma unroll 8
        for (int k = 0; k < NF; ++k) {
            const int kk = (k >> 2) & 7;
            const float4 a0 = As4[k * 32 + (ty ^ kk)];
            const float4 a1 = As4[k * 32 + 16 + (ty ^ kk)];
            const float4 b0 = Bs4[k * 32 + (tx ^ kk)];
            const float4 b1 = Bs4[k * 32 + 16 + (tx ^ kk)];
            const float av[2][4] = {{a0.x, a0.y, a0.z, a0.w},
                                    {a1.x, a1.y, a1.z, a1.w}};
            const float bv[2][4] = {{b0.x, b0.y, b0.z, b0.w},
                                    {b1.x, b1.y, b1.z, b1.w}};
#pragma unroll
            for (int p = 0; p < 2; ++p)
#pragma unroll
                for (int q = 0; q < 2; ++q)
#pragma unroll
                    for (int r = 0; r < 4; ++r)
#pragma unroll
                        for (int s = 0; s < 4; ++s)
                            c[p][q][r][s] = fmaf(av[p][r], bv[q][s], c[p][q][r][s]);
        }

        // Fused mining epilogue for this 128-col tile.
#pragma unroll
        for (int q = 0; q < 2; ++q)
#pragma unroll
            for (int s = 0; s < 4; ++s) {
                const int jcol = q * 64 + tx * 4 + s;
                const int lj = sLab[jcol];
                const int gj = jbase + jcol;
#pragma unroll
                for (int p = 0; p < 2; ++p)
#pragma unroll
                    for (int r = 0; r < 4; ++r) {
                        const float v = c[p][q][r][s];
                        const int girow = tb + p * 64 + ty * 4 + r;
                        if (lj == li[p][r]) {
                            if (gj != girow && v < minp[p][r]) {
                                minp[p][r] = v; pidx[p][r] = gj;
                            }
                        } else {
                            if (v > maxn[p][r]) {
                                maxn[p][r] = v; nidx[p][r] = gj;
                            }
                        }
                    }
            }
    }

    // Reduce across the 16 column-threads sharing each row (lanes 0-15 / 16-31
    // of each warp), then write dists + gather embeddings.
#pragma unroll
    for (int p = 0; p < 2; ++p)
#pragma unroll
        for (int r = 0; r < 4; ++r) {
            float mp = minp[p][r]; int pi = pidx[p][r];
            float mn = maxn[p][r]; int ni = nidx[p][r];
#pragma unroll
            for (int off = 8; off > 0; off >>= 1) {
                const float vp = __shfl_xor_sync(0xffffffffu, mp, off);
                const int   ip = __shfl_xor_sync(0xffffffffu, pi, off);
                const float vn = __shfl_xor_sync(0xffffffffu, mn, off);
                const int   in_ = __shfl_xor_sync(0xffffffffu, ni, off);
                if (vp < mp) { mp = vp; pi = ip; }
                if (vn > mn) { mn = vn; ni = in_; }
            }
            const int grow = tb + p * 64 + ty * 4 + r;
            const bool has_pos = (mp < INF);
            const size_t go = (size_t)d * NB + grow;
            if (tx == 0) {
                pos_dist[go] = has_pos ? mp : 0.0f;
                neg_dist[go] = has_pos ? mn : 0.0f;
            }
            float4* pdst = reinterpret_cast<float4*>(pos_embed) + go * (NF / 4);
            float4* ndst = reinterpret_cast<float4*>(neg_embed) + go * (NF / 4);
            if (has_pos) {
                const float4* psrc =
                    reinterpret_cast<const float4*>(embd) + (size_t)pi * (NF / 4);
                const float4* nsrc =
                    reinterpret_cast<const float4*>(embd) + (size_t)ni * (NF / 4);
                pdst[tx]      = psrc[tx];
                pdst[tx + 16] = psrc[tx + 16];
                ndst[tx]      = nsrc[tx];
                ndst[tx + 16] = nsrc[tx + 16];
            } else {
                const float4 z = {0.0f, 0.0f, 0.0f, 0.0f};
                pdst[tx] = z; pdst[tx + 16] = z;
                ndst[tx] = z; ndst[tx + 16] = z;
            }
        }
}

extern "C" void kernel_launch(void* const* d_in, const int* in_sizes, int n_in,
                              void* d_out, int out_size) {
    (void)in_sizes; (void)n_in; (void)out_size;
    const float* emb = (const float*)d_in[0];
    const unsigned int* labw = (const unsigned int*)d_in[1];

    float* out = (float*)d_out;
    // Output layout: pos_dist [D,B], neg_dist [D,B], pos_embed [D,B,F], neg_embed [D,B,F]
    float* pos_dist  = out;
    float* neg_dist  = out + (size_t)NDOM * NB;
    float* pos_embed = out + (size_t)2 * NDOM * NB;
    float* neg_embed = pos_embed + (size_t)NDOM * NB * NF;

    convert_labels_kernel<<<1, 256>>>(labw, NDOM * NB);

    cudaFuncSetAttribute(mine_kernel,
                         cudaFuncAttributeMaxDynamicSharedMemorySize, SMEM_BYTES);
    dim3 grid(NB / BM, NDOM);
    mine_kernel<<<grid, NTHREADS, SMEM_BYTES>>>(emb, pos_dist, neg_dist,
                                                pos_embed, neg_embed);
}

// round 4
// speedup vs baseline: 1.5531x; 1.5531x over previous
#include <cuda_runtime.h>
#include <cuda_bf16.h>
#include <cstdint>

#define NDOM 4
#define NB   8192
#define NF   128
#define BM   128
#define BN   128
#define NT   (NB / BN)
#define NTHREADS 256
#define MARGIN 4e-3f
#define MAXFLAGS 512
#define SLICES 4

// ---------------- SMEM layout (byte offsets) ----------------
#define OFF_AH  0u           /* 128x128 bf16 swizzled, 32KB */
#define OFF_AL  32768u
#define OFF_B   65536u       /* buf b at OFF_B + b*65536: hi 32KB, lo +32768 */
#define OFF_LAB 196608u      /* int[2][128] */
#define OFF_SCR 197632u      /* float[128*8] merge scratch */
#define SMEM_BYTES 201728u

__device__ int g_labels[NDOM * NB];
__device__ int g_flag_cnt;
__device__ int g_flags[MAXFLAGS];
__device__ unsigned long long g_best[MAXFLAGS];

// ---------------- helpers ----------------
__device__ __forceinline__ uint32_t smem_u32(const void* p) {
    uint32_t a;
    asm("{ .reg .u64 t; cvta.to.shared.u64 t, %1; cvt.u32.u64 %0, t; }"
        : "=r"(a) : "l"(p));
    return a;
}
__device__ __forceinline__ uint32_t fkey(float v) {
    uint32_t u = __float_as_uint(v);
    return (u & 0x80000000u) ? ~u : (u | 0x80000000u);
}
__device__ __forceinline__ void ldsm4(uint32_t* r, uint32_t addr) {
    asm volatile("ldmatrix.sync.aligned.m8n8.x4.shared.b16 {%0,%1,%2,%3}, [%4];"
                 : "=r"(r[0]), "=r"(r[1]), "=r"(r[2]), "=r"(r[3]) : "r"(addr));
}
__device__ __forceinline__ void mma16816(float* d, const uint32_t* a,
                                         const uint32_t* b) {
    asm volatile(
        "mma.sync.aligned.m16n8k16.row.col.f32.bf16.bf16.f32 "
        "{%0,%1,%2,%3}, {%4,%5,%6,%7}, {%8,%9}, {%0,%1,%2,%3};"
        : "+f"(d[0]), "+f"(d[1]), "+f"(d[2]), "+f"(d[3])
        : "r"(a[0]), "r"(a[1]), "r"(a[2]), "r"(a[3]), "r"(b[0]), "r"(b[1]));
}

// fp32 tile [128 rows x 128 k] -> bf16 hi/lo into swizzled row-major SMEM.
// byte(row,k) = row*256 + ((2k) ^ ((row&7)<<4))
__device__ __forceinline__ void load_convert(const float* __restrict__ src,
                                             char* __restrict__ sm,
                                             uint32_t hiOff, uint32_t loOff,
                                             int tid) {
    const float4* s4 = reinterpret_cast<const float4*>(src);
#pragma unroll
    for (int it = 0; it < 16; ++it) {
        const int f = it * NTHREADS + tid;
        const int row = f >> 5;
        const uint32_t byte = (uint32_t)row * 256u
            + ((((uint32_t)f & 31u) * 8u) ^ (((uint32_t)row & 7u) << 4));
        const float4 v = s4[f];
        __nv_bfloat162 h0 = __floats2bfloat162_rn(v.x, v.y);
        __nv_bfloat162 h1 = __floats2bfloat162_rn(v.z, v.w);
        const float rx = v.x - __bfloat162float(h0.x);
        const float ry = v.y - __bfloat162float(h0.y);
        const float rz = v.z - __bfloat162float(h1.x);
        const float rw = v.w - __bfloat162float(h1.y);
        __nv_bfloat162 l0 = __floats2bfloat162_rn(rx, ry);
        __nv_bfloat162 l1 = __floats2bfloat162_rn(rz, rw);
        uint2 hv, lv;
        hv.x = ((uint32_t)__bfloat16_as_ushort(h0.x)) | ((uint32_t)__bfloat16_as_ushort(h0.y) << 16);
        hv.y = ((uint32_t)__bfloat16_as_ushort(h1.x)) | ((uint32_t)__bfloat16_as_ushort(h1.y) << 16);
        lv.x = ((uint32_t)__bfloat16_as_ushort(l0.x)) | ((uint32_t)__bfloat16_as_ushort(l0.y) << 16);
        lv.y = ((uint32_t)__bfloat16_as_ushort(l1.x)) | ((uint32_t)__bfloat16_as_ushort(l1.y) << 16);
        *reinterpret_cast<uint2*>(sm + hiOff + byte) = hv;
        *reinterpret_cast<uint2*>(sm + loOff + byte) = lv;
    }
}

// ---------------- label normalization + flag reset ----------------
__global__ void convert_labels_kernel(const unsigned int* __restrict__ w, int n) {
    __shared__ int s_any;
    if (threadIdx.x == 0) { s_any = 0; g_flag_cnt = 0; }
    __syncthreads();
    int any = 0;
    for (int i = threadIdx.x; i < n / 2; i += blockDim.x)
        any |= (w[2 * i + 1] != 0u);
    if (any) atomicOr(&s_any, 1);
    for (int i = threadIdx.x; i < MAXFLAGS; i += blockDim.x) g_best[i] = 0ull;
    __syncthreads();
    const bool is64 = (s_any == 0);
    for (int i = threadIdx.x; i < n; i += blockDim.x)
        g_labels[i] = is64 ? (int)w[2 * i] : (int)w[i];
}

// ---------------- fused HMMA GEMM + top-2 mining ----------------
__global__ __launch_bounds__(NTHREADS, 1)
void mine_kernel(const float* __restrict__ emb,
                 float* __restrict__ pos_dist, float* __restrict__ neg_dist,
                 float* __restrict__ pos_embed, float* __restrict__ neg_embed) {
    extern __shared__ char smem[];
    const uint32_t sb = smem_u32(smem);
    const int tid = threadIdx.x;
    const int w = tid >> 5, L = tid & 31;
    const int wm = w & 3, wn = w >> 2;
    const int d = blockIdx.y;
    const int tb = blockIdx.x * BM;

    const float* __restrict__ embd = emb + (size_t)d * NB * NF;
    const int*   __restrict__ labd = g_labels + d * NB;

    // resident A tile + first B tile + first labels
    load_convert(embd + (size_t)tb * NF, smem, OFF_AH, OFF_AL, tid);
    load_convert(embd, smem, OFF_B, OFF_B + 32768u, tid);
    if (tid < 128) reinterpret_cast<int*>(smem + OFF_LAB)[tid] = labd[tid];

    // ldmatrix addressing (swizzle-folded constants)
    const uint32_t cxA = ((uint32_t)(L >> 4) * 16u) ^ (((uint32_t)L & 7u) << 4);
    const uint32_t cxB = ((uint32_t)((L >> 3) & 1) * 16u) ^ (((uint32_t)L & 7u) << 4);
    uint32_t aBase[2];
#pragma unroll
    for (int mt = 0; mt < 2; ++mt) {
        const int rowA = wm * 32 + mt * 16 + (L & 7) + ((L >> 3) & 1) * 8;
        aBase[mt] = sb + OFF_AH + (uint32_t)rowA * 256u;
    }
    uint32_t bRow[4];
#pragma unroll
    for (int bi = 0; bi < 4; ++bi) {
        const int rowB = wn * 64 + bi * 16 + (L & 7) + (L >> 4) * 8;
        bRow[bi] = (uint32_t)rowB * 256u;
    }

    // this thread's 4 result rows (mt,h)
    int li[4], growr[4];
#pragma unroll
    for (int s = 0; s < 4; ++s) {
        const int row = wm * 32 + (s >> 1) * 16 + (L >> 2) + (s & 1) * 8;
        growr[s] = tb + row;
        li[s] = labd[tb + row];
    }

    const float INF = __int_as_float(0x7f800000);
    float p1[4], p2[4], n1[4], n2[4];
    int i1[4], j1[4];
#pragma unroll
    for (int s = 0; s < 4; ++s) {
        p1[s] = INF; p2[s] = INF; n1[s] = -INF; n2[s] = -INF;
        i1[s] = -1; j1[s] = -1;
    }

    __syncthreads();

    for (int t = 0; t < NT; ++t) {
        if (t + 1 < NT) {
            const uint32_t nbo = OFF_B + (uint32_t)((t + 1) & 1) * 65536u;
            load_convert(embd + (size_t)(t + 1) * BN * NF, smem, nbo, nbo + 32768u, tid);
            if (tid < 128)
                reinterpret_cast<int*>(smem + OFF_LAB)[((t + 1) & 1) * 128 + tid] =
                    labd[(t + 1) * BN + tid];
        }

        // preload my 16 column labels for this tile
        const int* sl = reinterpret_cast<const int*>(smem + OFF_LAB) + (t & 1) * 128;
        int labc[8][2];
#pragma unroll
        for (int nt = 0; nt < 8; ++nt) {
            const int2 lv = *reinterpret_cast<const int2*>(
                sl + wn * 64 + nt * 8 + (L & 3) * 2);
            labc[nt][0] = lv.x; labc[nt][1] = lv.y;
        }

        float acc[2][8][4];
#pragma unroll
        for (int mt = 0; mt < 2; ++mt)
#pragma unroll
            for (int nt = 0; nt < 8; ++nt)
#pragma unroll
                for (int r = 0; r < 4; ++r) acc[mt][nt][r] = 0.0f;

        const uint32_t sbB = sb + OFF_B + (uint32_t)(t & 1) * 65536u;
#pragma unroll
        for (int ks = 0; ks < 8; ++ks) {
            const uint32_t offA = ((uint32_t)ks * 32u) ^ cxA;
            const uint32_t offB = ((uint32_t)ks * 32u) ^ cxB;
            uint32_t Ah[2][4], Al[2][4];
            ldsm4(Ah[0], aBase[0] + offA);
            ldsm4(Ah[1], aBase[1] + offA);
            ldsm4(Al[0], aBase[0] + 32768u + offA);
            ldsm4(Al[1], aBase[1] + 32768u + offA);
#pragma unroll
            for (int bi = 0; bi < 4; ++bi) {
                uint32_t Bh[4], Bl[4];
                ldsm4(Bh, sbB + bRow[bi] + offB);
                ldsm4(Bl, sbB + 32768u + bRow[bi] + offB);
#pragma unroll
                for (int mt = 0; mt < 2; ++mt) {
                    mma16816(acc[mt][2 * bi],     Ah[mt], Bh);
                    mma16816(acc[mt][2 * bi],     Al[mt], Bh);
                    mma16816(acc[mt][2 * bi],     Ah[mt], Bl);
                    mma16816(acc[mt][2 * bi + 1], Ah[mt], Bh + 2);
                    mma16816(acc[mt][2 * bi + 1], Al[mt], Bh + 2);
                    mma16816(acc[mt][2 * bi + 1], Ah[mt], Bl + 2);
                }
            }
        }

        // fused top-2 mining from register accumulators
        const int jb = t * BN + wn * 64 + (L & 3) * 2;
#pragma unroll
        for (int nt = 0; nt < 8; ++nt)
#pragma unroll
            for (int e = 0; e < 2; ++e) {
                const int lj = labc[nt][e];
                const int j = jb + nt * 8 + e;
#pragma unroll
                for (int s = 0; s < 4; ++s) {
                    const float v = acc[s >> 1][nt][(s & 1) * 2 + e];
                    if (lj == li[s]) {
                        if (j != growr[s]) {
                            if (v < p1[s]) { p2[s] = p1[s]; p1[s] = v; i1[s] = j; }
                            else if (v < p2[s]) p2[s] = v;
                        }
                    } else {
                        if (v > n1[s]) { n2[s] = n1[s]; n1[s] = v; j1[s] = j; }
                        else if (v > n2[s]) n2[s] = v;
                    }
                }
            }
        __syncthreads();
    }

    // reduce across the 4 lanes sharing each row
#pragma unroll
    for (int s = 0; s < 4; ++s) {
        float P1 = p1[s], P2 = p2[s], N1 = n1[s], N2 = n2[s];
        int I1 = i1[s], J1 = j1[s];
#pragma unroll
        for (int off = 1; off <= 2; off <<= 1) {
            const float oP1 = __shfl_xor_sync(0xffffffffu, P1, off);
            const float oP2 = __shfl_xor_sync(0xffffffffu, P2, off);
            const int   oI1 = __shfl_xor_sync(0xffffffffu, I1, off);
            const float oN1 = __shfl_xor_sync(0xffffffffu, N1, off);
            const float oN2 = __shfl_xor_sync(0xffffffffu, N2, off);
            const int   oJ1 = __shfl_xor_sync(0xffffffffu, J1, off);
            if (oP1 < P1) { P2 = fminf(P1, oP2); P1 = oP1; I1 = oI1; }
            else          { P2 = fminf(P2, oP1); }
            if (oN1 > N1) { N2 = fmaxf(N1, oN2); N1 = oN1; J1 = oJ1; }
            else          { N2 = fmaxf(N2, oN1); }
        }
        p1[s] = P1; p2[s] = P2; n1[s] = N1; n2[s] = N2; i1[s] = I1; j1[s] = J1;
    }

    // merge warp-column wn=1 -> wn=0 via scratch
    float* scr = reinterpret_cast<float*>(smem + OFF_SCR);
    if (wn == 1 && (L & 3) == 0) {
#pragma unroll
        for (int s = 0; s < 4; ++s) {
            const int row = wm * 32 + (s >> 1) * 16 + (L >> 2) + (s & 1) * 8;
            float* sr = scr + row * 8;
            sr[0] = p1[s]; reinterpret_cast<int*>(sr)[1] = i1[s]; sr[2] = p2[s];
            sr[3] = n1[s]; reinterpret_cast<int*>(sr)[4] = j1[s]; sr[5] = n2[s];
        }
    }
    __syncthreads();
    if (wn == 0 && (L & 3) == 0) {
#pragma unroll
        for (int s = 0; s < 4; ++s) {
            const int row = wm * 32 + (s >> 1) * 16 + (L >> 2) + (s & 1) * 8;
            float* sr = scr + row * 8;
            const float q1 = sr[0], q2 = sr[2], m1 = sr[3], m2 = sr[5];
            const int qi = reinterpret_cast<int*>(sr)[1];
            const int mi = reinterpret_cast<int*>(sr)[4];
            float P1 = p1[s], P2 = p2[s], N1 = n1[s], N2 = n2[s];
            int I1 = i1[s], J1 = j1[s];
            if (q1 < P1) { P2 = fminf(P1, q2); P1 = q1; I1 = qi; }
            else         { P2 = fminf(P2, q1); }
            if (m1 > N1) { N2 = fmaxf(N1, m2); N1 = m1; J1 = mi; }
            else         { N2 = fmaxf(N2, m1); }

            const bool has_pos = (P1 < INF);
            const size_t go = (size_t)d * NB + tb + row;
            pos_dist[go] = has_pos ? P1 : 0.0f;
            neg_dist[go] = has_pos ? N1 : 0.0f;
            reinterpret_cast<int*>(scr)[row * 8 + 6] = has_pos ? I1 : -1;
            reinterpret_cast<int*>(scr)[row * 8 + 7] = has_pos ? J1 : -1;
            if (has_pos) {
                const int basec = (int)((d * NB + tb + row) << 1);
                if (P2 - P1 < MARGIN) {
                    const int x = atomicAdd(&g_flag_cnt, 1);
                    if (x < MAXFLAGS) g_flags[x] = basec | 0;
                }
                if (N1 - N2 < MARGIN) {
                    const int x = atomicAdd(&g_flag_cnt, 1);
                    if (x < MAXFLAGS) g_flags[x] = basec | 1;
                }
            }
        }
    }
    __syncthreads();

    // cooperative embedding gather: copy c = row*2 + side, one warp per copy
    for (int c = w; c < 256; c += 8) {
        const int row = c >> 1, side = c & 1;
        const int idx = reinterpret_cast<int*>(scr)[row * 8 + 6 + side];
        float4* dst = reinterpret_cast<float4*>(
            (side ? neg_embed : pos_embed) + ((size_t)d * NB + tb + row) * NF);
        if (idx >= 0)
            dst[L] = reinterpret_cast<const float4*>(embd + (size_t)idx * NF)[L];
        else
            dst[L] = make_float4(0.f, 0.f, 0.f, 0.f);
    }
}

// ---------------- exact refine: full-row rescan for flagged (row, side) ----------------
__global__ void refine_scan_kernel(const float* __restrict__ emb) {
    const int f = blockIdx.x / SLICES, s = blockIdx.x % SLICES;
    const int cnt = min(g_flag_cnt, MAXFLAGS);
    if (f >= cnt) return;
    const int code = g_flags[f];
    const int side = code & 1, gr = code >> 1;
    const int d = gr >> 13, row = gr & (NB - 1);
    const float* __restrict__ embd = emb + (size_t)d * NB * NF;

    __shared__ float srow[NF];
    __shared__ int sli;
    if (threadIdx.x < NF) srow[threadIdx.x] = embd[(size_t)row * NF + threadIdx.x];
    if (threadIdx.x == 0) sli = g_labels[d * NB + row];
    __syncthreads();
    const int li = sli;
    const float4* a4 = reinterpret_cast<const float4*>(srow);

    unsigned long long best = 0ull;
    const int j0 = s * (NB / SLICES), jend = j0 + (NB / SLICES);
    for (int j = j0 + threadIdx.x; j < jend; j += blockDim.x) {
        const int lj = g_labels[d * NB + j];
        const bool valid = side ? (lj != li) : (lj == li && j != row);
        if (!valid) continue;
        const float4* b4 = reinterpret_cast<const float4*>(embd + (size_t)j * NF);
        float accv = 0.0f;
#pragma unroll
        for (int q = 0; q < 32; ++q) {
            const float4 av = a4[q], bv = b4[q];
            accv = fmaf(av.x, bv.x, accv);
            accv = fmaf(av.y, bv.y, accv);
            accv = fmaf(av.z, bv.z, accv);
            accv = fmaf(av.w, bv.w, accv);
        }
        uint32_t key = fkey(accv);
        if (!side) key = ~key;  // min side: invert ordering
        const unsigned long long pk =
            ((unsigned long long)key << 32) | (uint32_t)(NB - 1 - j);
        if (pk > best) best = pk;
    }
#pragma unroll
    for (int off = 16; off > 0; off >>= 1) {
        const unsigned long long o = __shfl_xor_sync(0xffffffffu, best, off);
        if (o > best) best = o;
    }
    if ((threadIdx.x & 31) == 0 && best)
        atomicMax(&g_best[f], best);
}

__global__ void refine_write_kernel(const float* __restrict__ emb,
                                    float* __restrict__ pos_dist,
                                    float* __restrict__ neg_dist,
                                    float* __restrict__ pos_embed,
                                    float* __restrict__ neg_embed) {
    const int f = blockIdx.x;
    const int cnt = min(g_flag_cnt, MAXFLAGS);
    if (f >= cnt) return;
    const int code = g_flags[f];
    const int side = code & 1, gr = code >> 1;
    const int d = gr >> 13, row = gr & (NB - 1);
    const unsigned long long pk = g_best[f];
    const uint32_t key = (uint32_t)(pk >> 32);
    const int j = NB - 1 - (int)(pk & 0xFFFFFFFFull);
    const uint32_t m = side ? key : ~key;
    const uint32_t u = (m & 0x80000000u) ? (m & 0x7FFFFFFFu) : ~m;
    const float v = __uint_as_float(u);

    const size_t go = (size_t)d * NB + row;
    float* dist = side ? neg_dist : pos_dist;
    float* embo = side ? neg_embed : pos_embed;
    if (threadIdx.x == 0) dist[go] = v;
    const float4* src =
        reinterpret_cast<const float4*>(emb + ((size_t)d * NB + j) * NF);
    reinterpret_cast<float4*>(embo + go * NF)[threadIdx.x] = src[threadIdx.x];
}

// ---------------- launch ----------------
extern "C" void kernel_launch(void* const* d_in, const int* in_sizes, int n_in,
                              void* d_out, int out_size) {
    (void)in_sizes; (void)n_in; (void)out_size;
    const float* emb = (const float*)d_in[0];
    const unsigned int* labw = (const unsigned int*)d_in[1];

    float* out = (float*)d_out;
    float* pos_dist  = out;
    float* neg_dist  = out + (size_t)NDOM * NB;
    float* pos_embed = out + (size_t)2 * NDOM * NB;
    float* neg_embed = pos_embed + (size_t)NDOM * NB * NF;

    convert_labels_kernel<<<1, 256>>>(labw, NDOM * NB);

    cudaFuncSetAttribute(mine_kernel,
                         cudaFuncAttributeMaxDynamicSharedMemorySize, SMEM_BYTES);
    dim3 grid(NB / BM, NDOM);
    mine_kernel<<<grid, NTHREADS, SMEM_BYTES>>>(emb, pos_dist, neg_dist,
                                                pos_embed, neg_embed);

    refine_scan_kernel<<<MAXFLAGS * SLICES, 128>>>(emb);
    refine_write_kernel<<<MAXFLAGS, 32>>>(emb, pos_dist, neg_dist,
                                          pos_embed, neg_embed);
}

// round 5
// speedup vs baseline: 1.9907x; 1.2817x over previous
#include <cuda_runtime.h>
#include <cuda_bf16.h>
#include <cstdint>

#define NDOM 4
#define NB   8192
#define NF   128
#define BM   128
#define BN   128
#define NT   (NB / BN)
#define NTHREADS 512
#define MARGIN 4e-3f
#define MAXFLAGS 512
#define SLICES 4

// ---------------- SMEM layout (byte offsets) ----------------
#define OFF_AH  0u            /* A hi 32KB (swizzled row-major bf16) */
#define OFF_AL  32768u        /* A lo 32KB */
#define OFF_B   65536u        /* buf b at OFF_B + b*65536: hi 32KB, lo +32768 */
#define OFF_SCR 196608u       /* [128 rows][4 wn][8 floats] = 16KB */
#define SMEM_BYTES 212992u

__device__ int g_labels[NDOM * NB];
__device__ int g_flag_cnt;
__device__ int g_flags[MAXFLAGS];
__device__ unsigned long long g_best[MAXFLAGS];
__device__ __nv_bfloat16 g_hi[NDOM * NB * NF];   // 8 MB
__device__ __nv_bfloat16 g_lo[NDOM * NB * NF];   // 8 MB

// ---------------- helpers ----------------
__device__ __forceinline__ uint32_t smem_u32(const void* p) {
    uint32_t a;
    asm("{ .reg .u64 t; cvta.to.shared.u64 t, %1; cvt.u32.u64 %0, t; }"
        : "=r"(a) : "l"(p));
    return a;
}
__device__ __forceinline__ uint32_t fkey(float v) {
    uint32_t u = __float_as_uint(v);
    return (u & 0x80000000u) ? ~u : (u | 0x80000000u);
}
__device__ __forceinline__ void ldsm4(uint32_t* r, uint32_t addr) {
    asm volatile("ldmatrix.sync.aligned.m8n8.x4.shared.b16 {%0,%1,%2,%3}, [%4];"
                 : "=r"(r[0]), "=r"(r[1]), "=r"(r[2]), "=r"(r[3]) : "r"(addr));
}
__device__ __forceinline__ void mma16816(float* d, const uint32_t* a,
                                         const uint32_t* b) {
    asm volatile(
        "mma.sync.aligned.m16n8k16.row.col.f32.bf16.bf16.f32 "
        "{%0,%1,%2,%3}, {%4,%5,%6,%7}, {%8,%9}, {%0,%1,%2,%3};"
        : "+f"(d[0]), "+f"(d[1]), "+f"(d[2]), "+f"(d[3])
        : "r"(a[0]), "r"(a[1]), "r"(a[2]), "r"(a[3]), "r"(b[0]), "r"(b[1]));
}
#define CP_ASYNC(dst, src) \
    asm volatile("cp.async.cg.shared.global [%0], [%1], 16;" :: "r"(dst), "l"(src))
#define CP_COMMIT() asm volatile("cp.async.commit_group;" ::: "memory")
#define CP_WAIT1()  asm volatile("cp.async.wait_group 1;" ::: "memory")
#define CP_WAIT0()  asm volatile("cp.async.wait_group 0;" ::: "memory")

// Copy one 128x128 bf16 tile (hi+lo) gmem -> swizzled smem via cp.async.
// Swizzled byte(row,k) = row*256 + ((2k) ^ ((row&7)<<4)); 16B chunk = 8 k.
__device__ __forceinline__ void copy_tile_async(
    uint32_t smem_hi, uint32_t smem_lo,
    const __nv_bfloat16* __restrict__ gh, const __nv_bfloat16* __restrict__ gl,
    int tid) {
#pragma unroll
    for (int it = 0; it < 8; ++it) {
        const int comp = it >> 2;
        const int rem = (it & 3) * NTHREADS + tid;   // 0..2047
        const int row = rem >> 4;
        const int kc = rem & 15;
        const uint32_t dstb = (uint32_t)row * 256u
            + (((uint32_t)kc * 16u) ^ (((uint32_t)row & 7u) << 4));
        const __nv_bfloat16* src = (comp ? gl : gh) + row * NF + kc * 8;
        const uint32_t dst = (comp ? smem_lo : smem_hi) + dstb;
        CP_ASYNC(dst, src);
    }
}

// ---------------- one-shot fp32 -> bf16 hi/lo split ----------------
__global__ void split_kernel(const float* __restrict__ emb) {
    const int i = blockIdx.x * blockDim.x + threadIdx.x;   // float4 index
    const float4 v = reinterpret_cast<const float4*>(emb)[i];
    __nv_bfloat162 h0 = __floats2bfloat162_rn(v.x, v.y);
    __nv_bfloat162 h1 = __floats2bfloat162_rn(v.z, v.w);
    const float rx = v.x - __bfloat162float(h0.x);
    const float ry = v.y - __bfloat162float(h0.y);
    const float rz = v.z - __bfloat162float(h1.x);
    const float rw = v.w - __bfloat162float(h1.y);
    __nv_bfloat162 l0 = __floats2bfloat162_rn(rx, ry);
    __nv_bfloat162 l1 = __floats2bfloat162_rn(rz, rw);
    uint2 hv, lv;
    hv.x = ((uint32_t)__bfloat16_as_ushort(h0.x)) | ((uint32_t)__bfloat16_as_ushort(h0.y) << 16);
    hv.y = ((uint32_t)__bfloat16_as_ushort(h1.x)) | ((uint32_t)__bfloat16_as_ushort(h1.y) << 16);
    lv.x = ((uint32_t)__bfloat16_as_ushort(l0.x)) | ((uint32_t)__bfloat16_as_ushort(l0.y) << 16);
    lv.y = ((uint32_t)__bfloat16_as_ushort(l1.x)) | ((uint32_t)__bfloat16_as_ushort(l1.y) << 16);
    reinterpret_cast<uint2*>(g_hi)[i] = hv;
    reinterpret_cast<uint2*>(g_lo)[i] = lv;
}

// ---------------- label normalization + flag reset ----------------
__global__ void convert_labels_kernel(const unsigned int* __restrict__ w, int n) {
    __shared__ int s_any;
    if (threadIdx.x == 0) { s_any = 0; g_flag_cnt = 0; }
    __syncthreads();
    int any = 0;
    for (int i = threadIdx.x; i < n / 2; i += blockDim.x)
        any |= (w[2 * i + 1] != 0u);
    if (any) atomicOr(&s_any, 1);
    for (int i = threadIdx.x; i < MAXFLAGS; i += blockDim.x) g_best[i] = 0ull;
    __syncthreads();
    const bool is64 = (s_any == 0);
    for (int i = threadIdx.x; i < n; i += blockDim.x)
        g_labels[i] = is64 ? (int)w[2 * i] : (int)w[i];
}

// ---------------- fused HMMA GEMM + top-2 mining ----------------
__global__ __launch_bounds__(NTHREADS, 1)
void mine_kernel(const float* __restrict__ emb,
                 float* __restrict__ pos_dist, float* __restrict__ neg_dist,
                 float* __restrict__ pos_embed, float* __restrict__ neg_embed) {
    extern __shared__ char smem[];
    const uint32_t sb = smem_u32(smem);
    const int tid = threadIdx.x;
    const int w = tid >> 5, L = tid & 31;
    const int wm = w & 3, wn = w >> 2;          // 4x4 warp grid
    const int d = blockIdx.y;
    const int tb = blockIdx.x * BM;

    const float* __restrict__ embd = emb + (size_t)d * NB * NF;
    const __nv_bfloat16* __restrict__ gh = g_hi + (size_t)d * NB * NF;
    const __nv_bfloat16* __restrict__ gl = g_lo + (size_t)d * NB * NF;
    const int* __restrict__ labd = g_labels + d * NB;

    // prologue: A tile (resident) + B tile 0, one async group
    copy_tile_async(sb + OFF_AH, sb + OFF_AL,
                    gh + (size_t)tb * NF, gl + (size_t)tb * NF, tid);
    copy_tile_async(sb + OFF_B, sb + OFF_B + 32768u, gh, gl, tid);
    CP_COMMIT();

    // ldmatrix addressing (swizzle-folded; verified in round 4)
    const uint32_t cxA = ((uint32_t)(L >> 4) * 16u) ^ (((uint32_t)L & 7u) << 4);
    const uint32_t cxB = ((uint32_t)((L >> 3) & 1) * 16u) ^ (((uint32_t)L & 7u) << 4);
    uint32_t aBase[2];
#pragma unroll
    for (int mt = 0; mt < 2; ++mt) {
        const int rowA = wm * 32 + mt * 16 + (L & 7) + ((L >> 3) & 1) * 8;
        aBase[mt] = sb + OFF_AH + (uint32_t)rowA * 256u;
    }
    uint32_t bRow[2];
#pragma unroll
    for (int bi = 0; bi < 2; ++bi) {
        const int rowB = wn * 32 + bi * 16 + (L & 7) + (L >> 4) * 8;
        bRow[bi] = (uint32_t)rowB * 256u;
    }

    // this thread's 4 result rows
    int li[4], growr[4];
#pragma unroll
    for (int s = 0; s < 4; ++s) {
        const int row = wm * 32 + (s >> 1) * 16 + (L >> 2) + (s & 1) * 8;
        growr[s] = tb + row;
        li[s] = labd[tb + row];
    }

    const float INF = __int_as_float(0x7f800000);
    float p1[4], p2[4], n1[4], n2[4];
    int i1[4], j1[4];
#pragma unroll
    for (int s = 0; s < 4; ++s) {
        p1[s] = INF; p2[s] = INF; n1[s] = -INF; n2[s] = -INF;
        i1[s] = -1; j1[s] = -1;
    }

    for (int t = 0; t < NT; ++t) {
        // prefetch B(t+1) into the other buffer (prev readers done: end-of-loop sync)
        if (t + 1 < NT) {
            const uint32_t bo = OFF_B + (uint32_t)((t + 1) & 1) * 65536u;
            copy_tile_async(sb + bo, sb + bo + 32768u,
                            gh + (size_t)(t + 1) * BN * NF,
                            gl + (size_t)(t + 1) * BN * NF, tid);
            CP_COMMIT();
            CP_WAIT1();             // tile t's group complete
        } else {
            CP_WAIT0();
        }
        __syncthreads();

        // column labels for this tile (L2-resident; hides under MMA)
        const int jb = t * BN + wn * 32 + (L & 3) * 2;
        int labc[4][2];
#pragma unroll
        for (int nt = 0; nt < 4; ++nt) {
            const int2 lv = *reinterpret_cast<const int2*>(labd + jb + nt * 8);
            labc[nt][0] = lv.x; labc[nt][1] = lv.y;
        }

        float acc[2][4][4];
#pragma unroll
        for (int mt = 0; mt < 2; ++mt)
#pragma unroll
            for (int nt = 0; nt < 4; ++nt)
#pragma unroll
                for (int r = 0; r < 4; ++r) acc[mt][nt][r] = 0.0f;

        const uint32_t sbB = sb + OFF_B + (uint32_t)(t & 1) * 65536u;
#pragma unroll
        for (int ks = 0; ks < 8; ++ks) {
            const uint32_t offA = ((uint32_t)ks * 32u) ^ cxA;
            const uint32_t offB = ((uint32_t)ks * 32u) ^ cxB;
            uint32_t Ah[2][4], Al[2][4];
            ldsm4(Ah[0], aBase[0] + offA);
            ldsm4(Ah[1], aBase[1] + offA);
            ldsm4(Al[0], aBase[0] + 32768u + offA);
            ldsm4(Al[1], aBase[1] + 32768u + offA);
#pragma unroll
            for (int bi = 0; bi < 2; ++bi) {
                uint32_t Bh[4], Bl[4];
                ldsm4(Bh, sbB + bRow[bi] + offB);
                ldsm4(Bl, sbB + 32768u + bRow[bi] + offB);
#pragma unroll
                for (int mt = 0; mt < 2; ++mt) {
                    mma16816(acc[mt][2 * bi],     Ah[mt], Bh);
                    mma16816(acc[mt][2 * bi],     Al[mt], Bh);
                    mma16816(acc[mt][2 * bi],     Ah[mt], Bl);
                    mma16816(acc[mt][2 * bi + 1], Ah[mt], Bh + 2);
                    mma16816(acc[mt][2 * bi + 1], Al[mt], Bh + 2);
                    mma16816(acc[mt][2 * bi + 1], Ah[mt], Bl + 2);
                }
            }
        }

        // fused top-2 mining from register accumulators
#pragma unroll
        for (int nt = 0; nt < 4; ++nt)
#pragma unroll
            for (int e = 0; e < 2; ++e) {
                const int lj = labc[nt][e];
                const int j = jb + nt * 8 + e;
#pragma unroll
                for (int s = 0; s < 4; ++s) {
                    const float v = acc[s >> 1][nt][(s & 1) * 2 + e];
                    if (lj == li[s]) {
                        if (j != growr[s]) {
                            if (v < p1[s]) { p2[s] = p1[s]; p1[s] = v; i1[s] = j; }
                            else if (v < p2[s]) p2[s] = v;
                        }
                    } else {
                        if (v > n1[s]) { n2[s] = n1[s]; n1[s] = v; j1[s] = j; }
                        else if (v > n2[s]) n2[s] = v;
                    }
                }
            }
        __syncthreads();   // everyone done reading buf t&1 before t+1 overwrites its pair
    }

    // reduce across the 4 lanes sharing each row (shfl offsets 1,2)
#pragma unroll
    for (int s = 0; s < 4; ++s) {
        float P1 = p1[s], P2 = p2[s], N1 = n1[s], N2 = n2[s];
        int I1 = i1[s], J1 = j1[s];
#pragma unroll
        for (int off = 1; off <= 2; off <<= 1) {
            const float oP1 = __shfl_xor_sync(0xffffffffu, P1, off);
            const float oP2 = __shfl_xor_sync(0xffffffffu, P2, off);
            const int   oI1 = __shfl_xor_sync(0xffffffffu, I1, off);
            const float oN1 = __shfl_xor_sync(0xffffffffu, N1, off);
            const float oN2 = __shfl_xor_sync(0xffffffffu, N2, off);
            const int   oJ1 = __shfl_xor_sync(0xffffffffu, J1, off);
            if (oP1 < P1) { P2 = fminf(P1, oP2); P1 = oP1; I1 = oI1; }
            else          { P2 = fminf(P2, oP1); }
            if (oN1 > N1) { N2 = fmaxf(N1, oN2); N1 = oN1; J1 = oJ1; }
            else          { N2 = fmaxf(N2, oN1); }
        }
        p1[s] = P1; p2[s] = P2; n1[s] = N1; n2[s] = N2; i1[s] = I1; j1[s] = J1;
    }

    // merge 4 warp-columns via scratch [row][wn][8]
    float* scr = reinterpret_cast<float*>(smem + OFF_SCR);
    if (wn > 0 && (L & 3) == 0) {
#pragma unroll
        for (int s = 0; s < 4; ++s) {
            const int row = wm * 32 + (s >> 1) * 16 + (L >> 2) + (s & 1) * 8;
            float* sr = scr + (row * 4 + wn) * 8;
            sr[0] = p1[s]; reinterpret_cast<int*>(sr)[1] = i1[s]; sr[2] = p2[s];
            sr[3] = n1[s]; reinterpret_cast<int*>(sr)[4] = j1[s]; sr[5] = n2[s];
        }
    }
    __syncthreads();
    if (wn == 0 && (L & 3) == 0) {
#pragma unroll
        for (int s = 0; s < 4; ++s) {
            const int row = wm * 32 + (s >> 1) * 16 + (L >> 2) + (s & 1) * 8;
            float P1 = p1[s], P2 = p2[s], N1 = n1[s], N2 = n2[s];
            int I1 = i1[s], J1 = j1[s];
#pragma unroll
            for (int o = 1; o < 4; ++o) {
                const float* sr = scr + (row * 4 + o) * 8;
                const float q1 = sr[0], q2 = sr[2], m1 = sr[3], m2 = sr[5];
                const int qi = reinterpret_cast<const int*>(sr)[1];
                const int mi = reinterpret_cast<const int*>(sr)[4];
                if (q1 < P1) { P2 = fminf(P1, q2); P1 = q1; I1 = qi; }
                else         { P2 = fminf(P2, q1); }
                if (m1 > N1) { N2 = fmaxf(N1, m2); N1 = m1; J1 = mi; }
                else         { N2 = fmaxf(N2, m1); }
            }
            const bool has_pos = (P1 < INF);
            const size_t go = (size_t)d * NB + tb + row;
            pos_dist[go] = has_pos ? P1 : 0.0f;
            neg_dist[go] = has_pos ? N1 : 0.0f;
            reinterpret_cast<int*>(scr)[(row * 4) * 8 + 6] = has_pos ? I1 : -1;
            reinterpret_cast<int*>(scr)[(row * 4) * 8 + 7] = has_pos ? J1 : -1;
            if (has_pos) {
                const int basec = (int)((d * NB + tb + row) << 1);
                if (P2 - P1 < MARGIN) {
                    const int x = atomicAdd(&g_flag_cnt, 1);
                    if (x < MAXFLAGS) g_flags[x] = basec | 0;
                }
                if (N1 - N2 < MARGIN) {
                    const int x = atomicAdd(&g_flag_cnt, 1);
                    if (x < MAXFLAGS) g_flags[x] = basec | 1;
                }
            }
        }
    }
    __syncthreads();

    // cooperative embedding gather: copy c = row*2 + side, one warp per copy
    for (int c = w; c < 256; c += 16) {
        const int row = c >> 1, side = c & 1;
        const int idx = reinterpret_cast<int*>(scr)[(row * 4) * 8 + 6 + side];
        float4* dst = reinterpret_cast<float4*>(
            (side ? neg_embed : pos_embed) + ((size_t)d * NB + tb + row) * NF);
        if (idx >= 0)
            dst[L] = reinterpret_cast<const float4*>(embd + (size_t)idx * NF)[L];
        else
            dst[L] = make_float4(0.f, 0.f, 0.f, 0.f);
    }
}

// ---------------- exact refine: full-row rescan for flagged (row, side) ----------------
__global__ void refine_scan_kernel(const float* __restrict__ emb) {
    const int f = blockIdx.x / SLICES, s = blockIdx.x % SLICES;
    const int cnt = min(g_flag_cnt, MAXFLAGS);
    if (f >= cnt) return;
    const int code = g_flags[f];
    const int side = code & 1, gr = code >> 1;
    const int d = gr >> 13, row = gr & (NB - 1);
    const float* __restrict__ embd = emb + (size_t)d * NB * NF;

    __shared__ float srow[NF];
    __shared__ int sli;
    if (threadIdx.x < NF) srow[threadIdx.x] = embd[(size_t)row * NF + threadIdx.x];
    if (threadIdx.x == 0) sli = g_labels[d * NB + row];
    __syncthreads();
    const int li = sli;
    const float4* a4 = reinterpret_cast<const float4*>(srow);

    unsigned long long best = 0ull;
    const int j0 = s * (NB / SLICES), jend = j0 + (NB / SLICES);
    for (int j = j0 + threadIdx.x; j < jend; j += blockDim.x) {
        const int lj = g_labels[d * NB + j];
        const bool valid = side ? (lj != li) : (lj == li && j != row);
        if (!valid) continue;
        const float4* b4 = reinterpret_cast<const float4*>(embd + (size_t)j * NF);
        float accv = 0.0f;
#pragma unroll
        for (int q = 0; q < 32; ++q) {
            const float4 av = a4[q], bv = b4[q];
            accv = fmaf(av.x, bv.x, accv);
            accv = fmaf(av.y, bv.y, accv);
            accv = fmaf(av.z, bv.z, accv);
            accv = fmaf(av.w, bv.w, accv);
        }
        uint32_t key = fkey(accv);
        if (!side) key = ~key;
        const unsigned long long pk =
            ((unsigned long long)key << 32) | (uint32_t)(NB - 1 - j);
        if (pk > best) best = pk;
    }
#pragma unroll
    for (int off = 16; off > 0; off >>= 1) {
        const unsigned long long o = __shfl_xor_sync(0xffffffffu, best, off);
        if (o > best) best = o;
    }
    if ((threadIdx.x & 31) == 0 && best)
        atomicMax(&g_best[f], best);
}

__global__ void refine_write_kernel(const float* __restrict__ emb,
                                    float* __restrict__ pos_dist,
                                    float* __restrict__ neg_dist,
                                    float* __restrict__ pos_embed,
                                    float* __restrict__ neg_embed) {
    const int f = blockIdx.x;
    const int cnt = min(g_flag_cnt, MAXFLAGS);
    if (f >= cnt) return;
    const int code = g_flags[f];
    const int side = code & 1, gr = code >> 1;
    const int d = gr >> 13, row = gr & (NB - 1);
    const unsigned long long pk = g_best[f];
    const uint32_t key = (uint32_t)(pk >> 32);
    const int j = NB - 1 - (int)(pk & 0xFFFFFFFFull);
    const uint32_t m = side ? key : ~key;
    const uint32_t u = (m & 0x80000000u) ? (m & 0x7FFFFFFFu) : ~m;
    const float v = __uint_as_float(u);

    const size_t go = (size_t)d * NB + row;
    float* dist = side ? neg_dist : pos_dist;
    float* embo = side ? neg_embed : pos_embed;
    if (threadIdx.x == 0) dist[go] = v;
    const float4* src =
        reinterpret_cast<const float4*>(emb + ((size_t)d * NB + j) * NF);
    reinterpret_cast<float4*>(embo + go * NF)[threadIdx.x] = src[threadIdx.x];
}

// ---------------- launch ----------------
extern "C" void kernel_launch(void* const* d_in, const int* in_sizes, int n_in,
                              void* d_out, int out_size) {
    (void)in_sizes; (void)n_in; (void)out_size;
    const float* emb = (const float*)d_in[0];
    const unsigned int* labw = (const unsigned int*)d_in[1];

    float* out = (float*)d_out;
    float* pos_dist  = out;
    float* neg_dist  = out + (size_t)NDOM * NB;
    float* pos_embed = out + (size_t)2 * NDOM * NB;
    float* neg_embed = pos_embed + (size_t)NDOM * NB * NF;

    convert_labels_kernel<<<1, 256>>>(labw, NDOM * NB);
    split_kernel<<<(NDOM * NB * NF / 4) / 256, 256>>>(emb);

    cudaFuncSetAttribute(mine_kernel,
                         cudaFuncAttributeMaxDynamicSharedMemorySize, SMEM_BYTES);
    dim3 grid(NB / BM, NDOM);
    mine_kernel<<<grid, NTHREADS, SMEM_BYTES>>>(emb, pos_dist, neg_dist,
                                                pos_embed, neg_embed);

    refine_scan_kernel<<<MAXFLAGS * SLICES, 128>>>(emb);
    refine_write_kernel<<<MAXFLAGS, 32>>>(emb, pos_dist, neg_dist,
                                          pos_embed, neg_embed);
}

// round 6
// speedup vs baseline: 2.0592x; 1.0344x over previous
#include <cuda_runtime.h>
#include <cuda_fp16.h>
#include <cstdint>

#define NDOM 4
#define NB   8192
#define NF   128
#define BM   128
#define BN   128
#define NT   (NB / BN)
#define NTHREADS 512
#define MARGIN 2e-4f
#define MAXFLAGS 512
#define SLICES 4

// ---------------- SMEM layout (byte offsets) ----------------
#define OFF_AH  0u            /* A hi 32KB (swizzled row-major fp16) */
#define OFF_AL  32768u        /* A lo 32KB */
#define OFF_B   65536u        /* buf b at OFF_B + b*65536: hi 32KB, lo +32768 */
#define OFF_SCR 196608u       /* [128 rows][4 wn][8 floats] = 16KB */
#define SMEM_BYTES 212992u

__device__ int g_labels[NDOM * NB];
__device__ int g_flag_cnt;
__device__ int g_flags[MAXFLAGS];
__device__ unsigned long long g_best[MAXFLAGS];
__device__ __half g_hi[NDOM * NB * NF];   // 8 MB
__device__ __half g_lo[NDOM * NB * NF];   // 8 MB

// ---------------- helpers ----------------
__device__ __forceinline__ uint32_t smem_u32(const void* p) {
    uint32_t a;
    asm("{ .reg .u64 t; cvta.to.shared.u64 t, %1; cvt.u32.u64 %0, t; }"
        : "=r"(a) : "l"(p));
    return a;
}
__device__ __forceinline__ uint32_t fkey(float v) {
    uint32_t u = __float_as_uint(v);
    return (u & 0x80000000u) ? ~u : (u | 0x80000000u);
}
__device__ __forceinline__ void ldsm4(uint32_t* r, uint32_t addr) {
    asm volatile("ldmatrix.sync.aligned.m8n8.x4.shared.b16 {%0,%1,%2,%3}, [%4];"
                 : "=r"(r[0]), "=r"(r[1]), "=r"(r[2]), "=r"(r[3]) : "r"(addr));
}
__device__ __forceinline__ void mma16816(float* d, const uint32_t* a,
                                         const uint32_t* b) {
    asm volatile(
        "mma.sync.aligned.m16n8k16.row.col.f32.f16.f16.f32 "
        "{%0,%1,%2,%3}, {%4,%5,%6,%7}, {%8,%9}, {%0,%1,%2,%3};"
        : "+f"(d[0]), "+f"(d[1]), "+f"(d[2]), "+f"(d[3])
        : "r"(a[0]), "r"(a[1]), "r"(a[2]), "r"(a[3]), "r"(b[0]), "r"(b[1]));
}
#define CP_ASYNC(dst, src) \
    asm volatile("cp.async.cg.shared.global [%0], [%1], 16;" :: "r"(dst), "l"(src))
#define CP_COMMIT() asm volatile("cp.async.commit_group;" ::: "memory")
#define CP_WAIT1()  asm volatile("cp.async.wait_group 1;" ::: "memory")
#define CP_WAIT0()  asm volatile("cp.async.wait_group 0;" ::: "memory")

// Copy one 128x128 fp16 tile (hi+lo) gmem -> swizzled smem via cp.async.
// Swizzled byte(row,k) = row*256 + ((2k) ^ ((row&7)<<4)); 16B chunk = 8 k.
__device__ __forceinline__ void copy_tile_async(
    uint32_t smem_hi, uint32_t smem_lo,
    const __half* __restrict__ gh, const __half* __restrict__ gl,
    int tid) {
#pragma unroll
    for (int it = 0; it < 8; ++it) {
        const int comp = it >> 2;
        const int rem = (it & 3) * NTHREADS + tid;   // 0..2047
        const int row = rem >> 4;
        const int kc = rem & 15;
        const uint32_t dstb = (uint32_t)row * 256u
            + (((uint32_t)kc * 16u) ^ (((uint32_t)row & 7u) << 4));
        const __half* src = (comp ? gl : gh) + row * NF + kc * 8;
        const uint32_t dst = (comp ? smem_lo : smem_hi) + dstb;
        CP_ASYNC(dst, src);
    }
}

// ---------------- one-shot fp32 -> fp16 hi/lo split ----------------
__global__ void split_kernel(const float* __restrict__ emb) {
    const int i = blockIdx.x * blockDim.x + threadIdx.x;   // float4 index
    const float4 v = reinterpret_cast<const float4*>(emb)[i];
    const __half hx = __float2half_rn(v.x), hy = __float2half_rn(v.y);
    const __half hz = __float2half_rn(v.z), hw = __float2half_rn(v.w);
    const __half lx = __float2half_rn(v.x - __half2float(hx));
    const __half ly = __float2half_rn(v.y - __half2float(hy));
    const __half lz = __float2half_rn(v.z - __half2float(hz));
    const __half lw = __float2half_rn(v.w - __half2float(hw));
    uint2 hv, lv;
    hv.x = ((uint32_t)__half_as_ushort(hx)) | ((uint32_t)__half_as_ushort(hy) << 16);
    hv.y = ((uint32_t)__half_as_ushort(hz)) | ((uint32_t)__half_as_ushort(hw) << 16);
    lv.x = ((uint32_t)__half_as_ushort(lx)) | ((uint32_t)__half_as_ushort(ly) << 16);
    lv.y = ((uint32_t)__half_as_ushort(lz)) | ((uint32_t)__half_as_ushort(lw) << 16);
    reinterpret_cast<uint2*>(g_hi)[i] = hv;
    reinterpret_cast<uint2*>(g_lo)[i] = lv;
}

// ---------------- label normalization + flag reset ----------------
__global__ void convert_labels_kernel(const unsigned int* __restrict__ w, int n) {
    __shared__ int s_any;
    if (threadIdx.x == 0) { s_any = 0; g_flag_cnt = 0; }
    __syncthreads();
    int any = 0;
    for (int i = threadIdx.x; i < n / 2; i += blockDim.x)
        any |= (w[2 * i + 1] != 0u);
    if (any) atomicOr(&s_any, 1);
    for (int i = threadIdx.x; i < MAXFLAGS; i += blockDim.x) g_best[i] = 0ull;
    __syncthreads();
    const bool is64 = (s_any == 0);
    for (int i = threadIdx.x; i < n; i += blockDim.x)
        g_labels[i] = is64 ? (int)w[2 * i] : (int)w[i];
}

// ---------------- fused HMMA GEMM + top-2 mining ----------------
__global__ __launch_bounds__(NTHREADS, 1)
void mine_kernel(const float* __restrict__ emb,
                 float* __restrict__ pos_dist, float* __restrict__ neg_dist,
                 float* __restrict__ pos_embed, float* __restrict__ neg_embed) {
    extern __shared__ char smem[];
    const uint32_t sb = smem_u32(smem);
    const int tid = threadIdx.x;
    const int w = tid >> 5, L = tid & 31;
    const int wm = w & 3, wn = w >> 2;          // 4x4 warp grid
    const int d = blockIdx.y;
    const int tb = blockIdx.x * BM;

    const float* __restrict__ embd = emb + (size_t)d * NB * NF;
    const __half* __restrict__ gh = g_hi + (size_t)d * NB * NF;
    const __half* __restrict__ gl = g_lo + (size_t)d * NB * NF;
    const int* __restrict__ labd = g_labels + d * NB;

    // prologue: A tile (resident) + B tile 0, one async group
    copy_tile_async(sb + OFF_AH, sb + OFF_AL,
                    gh + (size_t)tb * NF, gl + (size_t)tb * NF, tid);
    copy_tile_async(sb + OFF_B, sb + OFF_B + 32768u, gh, gl, tid);
    CP_COMMIT();

    // ldmatrix addressing (swizzle-folded; verified rounds 4-5)
    const uint32_t cxA = ((uint32_t)(L >> 4) * 16u) ^ (((uint32_t)L & 7u) << 4);
    const uint32_t cxB = ((uint32_t)((L >> 3) & 1) * 16u) ^ (((uint32_t)L & 7u) << 4);
    uint32_t aBase[2];
#pragma unroll
    for (int mt = 0; mt < 2; ++mt) {
        const int rowA = wm * 32 + mt * 16 + (L & 7) + ((L >> 3) & 1) * 8;
        aBase[mt] = sb + OFF_AH + (uint32_t)rowA * 256u;
    }
    uint32_t bRow[2];
#pragma unroll
    for (int bi = 0; bi < 2; ++bi) {
        const int rowB = wn * 32 + bi * 16 + (L & 7) + (L >> 4) * 8;
        bRow[bi] = (uint32_t)rowB * 256u;
    }

    // this thread's 4 result rows: row(s) = rbase + (s&1)*8 + (s>>1)*16
    const int rbase = wm * 32 + (L >> 2);
    int li[4];
#pragma unroll
    for (int s = 0; s < 4; ++s)
        li[s] = labd[tb + rbase + (s & 1) * 8 + (s >> 1) * 16];

    const float INF = __int_as_float(0x7f800000);
    float p1[4], p2[4], n1[4], n2[4];
    int i1[4], j1[4];
#pragma unroll
    for (int s = 0; s < 4; ++s) {
        p1[s] = INF; p2[s] = INF; n1[s] = -INF; n2[s] = -INF;
        i1[s] = -1; j1[s] = -1;
    }

    for (int t = 0; t < NT; ++t) {
        if (t + 1 < NT) {
            const uint32_t bo = OFF_B + (uint32_t)((t + 1) & 1) * 65536u;
            copy_tile_async(sb + bo, sb + bo + 32768u,
                            gh + (size_t)(t + 1) * BN * NF,
                            gl + (size_t)(t + 1) * BN * NF, tid);
            CP_COMMIT();
            CP_WAIT1();
        } else {
            CP_WAIT0();
        }
        __syncthreads();

        const int jb = t * BN + wn * 32 + (L & 3) * 2;
        int labc[4][2];
#pragma unroll
        for (int nt = 0; nt < 4; ++nt) {
            const int2 lv = *reinterpret_cast<const int2*>(labd + jb + nt * 8);
            labc[nt][0] = lv.x; labc[nt][1] = lv.y;
        }

        float acc[2][4][4];
#pragma unroll
        for (int mt = 0; mt < 2; ++mt)
#pragma unroll
            for (int nt = 0; nt < 4; ++nt)
#pragma unroll
                for (int r = 0; r < 4; ++r) acc[mt][nt][r] = 0.0f;

        const uint32_t sbB = sb + OFF_B + (uint32_t)(t & 1) * 65536u;
#pragma unroll
        for (int ks = 0; ks < 8; ++ks) {
            const uint32_t offA = ((uint32_t)ks * 32u) ^ cxA;
            const uint32_t offB = ((uint32_t)ks * 32u) ^ cxB;
            // load all fragments for this kstep (32 regs)
            uint32_t Ah[2][4], Al[2][4], Bh[2][4], Bl[2][4];
            ldsm4(Ah[0], aBase[0] + offA);
            ldsm4(Ah[1], aBase[1] + offA);
            ldsm4(Bh[0], sbB + bRow[0] + offB);
            ldsm4(Bh[1], sbB + bRow[1] + offB);
            ldsm4(Al[0], aBase[0] + 32768u + offA);
            ldsm4(Al[1], aBase[1] + 32768u + offA);
            ldsm4(Bl[0], sbB + 32768u + bRow[0] + offB);
            ldsm4(Bl[1], sbB + 32768u + bRow[1] + offB);
            // pass 1: Ah*Bh -> 8 independent accumulators
#pragma unroll
            for (int bi = 0; bi < 2; ++bi)
#pragma unroll
                for (int mt = 0; mt < 2; ++mt) {
                    mma16816(acc[mt][2 * bi],     Ah[mt], Bh[bi]);
                    mma16816(acc[mt][2 * bi + 1], Ah[mt], Bh[bi] + 2);
                }
            // pass 2: Al*Bh (dep distance 8)
#pragma unroll
            for (int bi = 0; bi < 2; ++bi)
#pragma unroll
                for (int mt = 0; mt < 2; ++mt) {
                    mma16816(acc[mt][2 * bi],     Al[mt], Bh[bi]);
                    mma16816(acc[mt][2 * bi + 1], Al[mt], Bh[bi] + 2);
                }
            // pass 3: Ah*Bl
#pragma unroll
            for (int bi = 0; bi < 2; ++bi)
#pragma unroll
                for (int mt = 0; mt < 2; ++mt) {
                    mma16816(acc[mt][2 * bi],     Ah[mt], Bl[bi]);
                    mma16816(acc[mt][2 * bi + 1], Ah[mt], Bl[bi] + 2);
                }
        }

        // fused top-2 mining from register accumulators
#pragma unroll
        for (int nt = 0; nt < 4; ++nt)
#pragma unroll
            for (int e = 0; e < 2; ++e) {
                const int lj = labc[nt][e];
                const int j = jb + nt * 8 + e;
#pragma unroll
                for (int s = 0; s < 4; ++s) {
                    const float v = acc[s >> 1][nt][(s & 1) * 2 + e];
                    if (lj == li[s]) {
                        const int growr = tb + rbase + (s & 1) * 8 + (s >> 1) * 16;
                        if (j != growr) {
                            if (v < p1[s]) { p2[s] = p1[s]; p1[s] = v; i1[s] = j; }
                            else if (v < p2[s]) p2[s] = v;
                        }
                    } else {
                        if (v > n1[s]) { n2[s] = n1[s]; n1[s] = v; j1[s] = j; }
                        else if (v > n2[s]) n2[s] = v;
                    }
                }
            }
        __syncthreads();
    }

    // reduce across the 4 lanes sharing each row (shfl offsets 1,2)
#pragma unroll
    for (int s = 0; s < 4; ++s) {
        float P1 = p1[s], P2 = p2[s], N1 = n1[s], N2 = n2[s];
        int I1 = i1[s], J1 = j1[s];
#pragma unroll
        for (int off = 1; off <= 2; off <<= 1) {
            const float oP1 = __shfl_xor_sync(0xffffffffu, P1, off);
            const float oP2 = __shfl_xor_sync(0xffffffffu, P2, off);
            const int   oI1 = __shfl_xor_sync(0xffffffffu, I1, off);
            const float oN1 = __shfl_xor_sync(0xffffffffu, N1, off);
            const float oN2 = __shfl_xor_sync(0xffffffffu, N2, off);
            const int   oJ1 = __shfl_xor_sync(0xffffffffu, J1, off);
            if (oP1 < P1) { P2 = fminf(P1, oP2); P1 = oP1; I1 = oI1; }
            else          { P2 = fminf(P2, oP1); }
            if (oN1 > N1) { N2 = fmaxf(N1, oN2); N1 = oN1; J1 = oJ1; }
            else          { N2 = fmaxf(N2, oN1); }
        }
        p1[s] = P1; p2[s] = P2; n1[s] = N1; n2[s] = N2; i1[s] = I1; j1[s] = J1;
    }

    // merge 4 warp-columns via scratch [row][wn][8]
    float* scr = reinterpret_cast<float*>(smem + OFF_SCR);
    if (wn > 0 && (L & 3) == 0) {
#pragma unroll
        for (int s = 0; s < 4; ++s) {
            const int row = rbase + (s & 1) * 8 + (s >> 1) * 16;
            float* sr = scr + (row * 4 + wn) * 8;
            sr[0] = p1[s]; reinterpret_cast<int*>(sr)[1] = i1[s]; sr[2] = p2[s];
            sr[3] = n1[s]; reinterpret_cast<int*>(sr)[4] = j1[s]; sr[5] = n2[s];
        }
    }
    __syncthreads();
    if (wn == 0 && (L & 3) == 0) {
#pragma unroll
        for (int s = 0; s < 4; ++s) {
            const int row = rbase + (s & 1) * 8 + (s >> 1) * 16;
            float P1 = p1[s], P2 = p2[s], N1 = n1[s], N2 = n2[s];
            int I1 = i1[s], J1 = j1[s];
#pragma unroll
            for (int o = 1; o < 4; ++o) {
                const float* sr = scr + (row * 4 + o) * 8;
                const float q1 = sr[0], q2 = sr[2], m1 = sr[3], m2 = sr[5];
                const int qi = reinterpret_cast<const int*>(sr)[1];
                const int mi = reinterpret_cast<const int*>(sr)[4];
                if (q1 < P1) { P2 = fminf(P1, q2); P1 = q1; I1 = qi; }
                else         { P2 = fminf(P2, q1); }
                if (m1 > N1) { N2 = fmaxf(N1, m2); N1 = m1; J1 = mi; }
                else         { N2 = fmaxf(N2, m1); }
            }
            const bool has_pos = (P1 < INF);
            const size_t go = (size_t)d * NB + tb + row;
            pos_dist[go] = has_pos ? P1 : 0.0f;
            neg_dist[go] = has_pos ? N1 : 0.0f;
            reinterpret_cast<int*>(scr)[(row * 4) * 8 + 6] = has_pos ? I1 : -1;
            reinterpret_cast<int*>(scr)[(row * 4) * 8 + 7] = has_pos ? J1 : -1;
            if (has_pos) {
                const int basec = (int)((d * NB + tb + row) << 1);
                if (P2 - P1 < MARGIN) {
                    const int x = atomicAdd(&g_flag_cnt, 1);
                    if (x < MAXFLAGS) g_flags[x] = basec | 0;
                }
                if (N1 - N2 < MARGIN) {
                    const int x = atomicAdd(&g_flag_cnt, 1);
                    if (x < MAXFLAGS) g_flags[x] = basec | 1;
                }
            }
        }
    }
    __syncthreads();

    // cooperative embedding gather: copy c = row*2 + side, one warp per copy
    for (int c = w; c < 256; c += 16) {
        const int row = c >> 1, side = c & 1;
        const int idx = reinterpret_cast<int*>(scr)[(row * 4) * 8 + 6 + side];
        float4* dst = reinterpret_cast<float4*>(
            (side ? neg_embed : pos_embed) + ((size_t)d * NB + tb + row) * NF);
        if (idx >= 0)
            dst[L] = reinterpret_cast<const float4*>(embd + (size_t)idx * NF)[L];
        else
            dst[L] = make_float4(0.f, 0.f, 0.f, 0.f);
    }
}

// ---------------- exact refine: full-row rescan for flagged (row, side) ----------------
__global__ void refine_scan_kernel(const float* __restrict__ emb) {
    const int f = blockIdx.x / SLICES, s = blockIdx.x % SLICES;
    const int cnt = min(g_flag_cnt, MAXFLAGS);
    if (f >= cnt) return;
    const int code = g_flags[f];
    const int side = code & 1, gr = code >> 1;
    const int d = gr >> 13, row = gr & (NB - 1);
    const float* __restrict__ embd = emb + (size_t)d * NB * NF;

    __shared__ float srow[NF];
    __shared__ int sli;
    if (threadIdx.x < NF) srow[threadIdx.x] = embd[(size_t)row * NF + threadIdx.x];
    if (threadIdx.x == 0) sli = g_labels[d * NB + row];
    __syncthreads();
    const int li = sli;
    const float4* a4 = reinterpret_cast<const float4*>(srow);

    unsigned long long best = 0ull;
    const int j0 = s * (NB / SLICES), jend = j0 + (NB / SLICES);
    for (int j = j0 + threadIdx.x; j < jend; j += blockDim.x) {
        const int lj = g_labels[d * NB + j];
        const bool valid = side ? (lj != li) : (lj == li && j != row);
        if (!valid) continue;
        const float4* b4 = reinterpret_cast<const float4*>(embd + (size_t)j * NF);
        float accv = 0.0f;
#pragma unroll
        for (int q = 0; q < 32; ++q) {
            const float4 av = a4[q], bv = b4[q];
            accv = fmaf(av.x, bv.x, accv);
            accv = fmaf(av.y, bv.y, accv);
            accv = fmaf(av.z, bv.z, accv);
            accv = fmaf(av.w, bv.w, accv);
        }
        uint32_t key = fkey(accv);
        if (!side) key = ~key;
        const unsigned long long pk =
            ((unsigned long long)key << 32) | (uint32_t)(NB - 1 - j);
        if (pk > best) best = pk;
    }
#pragma unroll
    for (int off = 16; off > 0; off >>= 1) {
        const unsigned long long o = __shfl_xor_sync(0xffffffffu, best, off);
        if (o > best) best = o;
    }
    if ((threadIdx.x & 31) == 0 && best)
        atomicMax(&g_best[f], best);
}

__global__ void refine_write_kernel(const float* __restrict__ emb,
                                    float* __restrict__ pos_dist,
                                    float* __restrict__ neg_dist,
                                    float* __restrict__ pos_embed,
                                    float* __restrict__ neg_embed) {
    const int f = blockIdx.x;
    const int cnt = min(g_flag_cnt, MAXFLAGS);
    if (f >= cnt) return;
    const int code = g_flags[f];
    const int side = code & 1, gr = code >> 1;
    const int d = gr >> 13, row = gr & (NB - 1);
    const unsigned long long pk = g_best[f];
    const uint32_t key = (uint32_t)(pk >> 32);
    const int j = NB - 1 - (int)(pk & 0xFFFFFFFFull);
    const uint32_t m = side ? key : ~key;
    const uint32_t u = (m & 0x80000000u) ? (m & 0x7FFFFFFFu) : ~m;
    const float v = __uint_as_float(u);

    const size_t go = (size_t)d * NB + row;
    float* dist = side ? neg_dist : pos_dist;
    float* embo = side ? neg_embed : pos_embed;
    if (threadIdx.x == 0) dist[go] = v;
    const float4* src =
        reinterpret_cast<const float4*>(emb + ((size_t)d * NB + j) * NF);
    reinterpret_cast<float4*>(embo + go * NF)[threadIdx.x] = src[threadIdx.x];
}

// ---------------- launch ----------------
extern "C" void kernel_launch(void* const* d_in, const int* in_sizes, int n_in,
                              void* d_out, int out_size) {
    (void)in_sizes; (void)n_in; (void)out_size;
    const float* emb = (const float*)d_in[0];
    const unsigned int* labw = (const unsigned int*)d_in[1];

    float* out = (float*)d_out;
    float* pos_dist  = out;
    float* neg_dist  = out + (size_t)NDOM * NB;
    float* pos_embed = out + (size_t)2 * NDOM * NB;
    float* neg_embed = pos_embed + (size_t)NDOM * NB * NF;

    convert_labels_kernel<<<1, 256>>>(labw, NDOM * NB);
    split_kernel<<<(NDOM * NB * NF / 4) / 256, 256>>>(emb);

    cudaFuncSetAttribute(mine_kernel,
                         cudaFuncAttributeMaxDynamicSharedMemorySize, SMEM_BYTES);
    dim3 grid(NB / BM, NDOM);
    mine_kernel<<<grid, NTHREADS, SMEM_BYTES>>>(emb, pos_dist, neg_dist,
                                                pos_embed, neg_embed);

    refine_scan_kernel<<<MAXFLAGS * SLICES, 128>>>(emb);
    refine_write_kernel<<<MAXFLAGS, 32>>>(emb, pos_dist, neg_dist,
                                          pos_embed, neg_embed);
}